// round 13
// baseline (speedup 1.0000x reference)
#include <cuda_runtime.h>
#include <math.h>

// Problem constants (fixed by the reference)
#define POOL   100
#define NTASKS 10
#define NB_PT  (POOL / NTASKS)       // 10
#define PLEN   8
#define EMBD   768
#define BATCH  512
#define ED4    (EMBD / 4)            // 192

#define COPY_BLOCKS 2560

// Scratch (allocation-free per harness rules)
__device__ float g_sim[BATCH * POOL];
__device__ float g_w1[POOL * EMBD];  // e^2 * diag
__device__ float g_w2[POOL * EMBD];  // e^2 * diag^2
__device__ float g_w3[POOL * EMBD];  // e^2

// ---------------------------------------------------------------------------
// Kernel 1: wvec — scalar thread per (k,d): 76800 threads, 300 blocks.
//   diag = sum_l e_p[k,l,d]^2 ; w3 = e_a^2 ; w1 = w3*diag ; w2 = w1*diag.
//   8 independent coalesced loads per thread (warp = 128B lines).
// ---------------------------------------------------------------------------
__global__ void wvec_kernel(const float* __restrict__ e_a,
                            const float* __restrict__ e_p) {
    int i = blockIdx.x * blockDim.x + threadIdx.x;   // over POOL*EMBD
    if (i >= POOL * EMBD) return;
    int k = i / EMBD;
    int d = i % EMBD;

    const float* epk = e_p + (size_t)k * PLEN * EMBD + d;
    float diag = 0.f;
#pragma unroll
    for (int l = 0; l < PLEN; l++) {
        float v = epk[l * EMBD];
        diag += v * v;
    }
    float e  = e_a[i];
    float e2 = e * e;
    float w1 = e2 * diag;
    g_w3[i] = e2;
    g_w1[i] = w1;
    g_w2[i] = w1 * diag;
}

// ---------------------------------------------------------------------------
// Kernel 2: sim — warp per (b,k) pair. 6400 blocks x 256 (worst case);
// warps with pair-index >= BATCH*task_end exit. No smem, no sync.
//   sim[b,k] = Sx2w1 / (sqrt(Sx2w2)*sqrt(Sx2w3)),  x2 = xq^2.
// ---------------------------------------------------------------------------
__global__ void __launch_bounds__(256) sim_kernel(
        const float* __restrict__ x_querry,
        const int*   __restrict__ task_id_p) {
    const int task_end = (*task_id_p + 1) * NB_PT;
    const int p    = (blockIdx.x * 256 + threadIdx.x) >> 5;   // pair index
    const int lane = threadIdx.x & 31;
    if (p >= BATCH * task_end) return;
    const int b = p / task_end;
    const int k = p % task_end;
    const int row = POOL - task_end + k;

    const float4* xq4 = (const float4*)(x_querry +
                        ((size_t)b * POOL + row) * EMBD);
    const size_t kb = (size_t)k * ED4;
    const float4* w14 = (const float4*)g_w1 + kb;
    const float4* w24 = (const float4*)g_w2 + kb;
    const float4* w34 = (const float4*)g_w3 + kb;

    float s1 = 0.f, s2 = 0.f, s3 = 0.f;
#pragma unroll
    for (int j = 0; j < ED4 / 32; j++) {   // 6 iterations
        int idx = lane + j * 32;
        float4 x  = xq4[idx];
        float4 a1 = w14[idx];
        float4 a2 = w24[idx];
        float4 a3 = w34[idx];
        float xx;
        xx = x.x * x.x; s1 += xx * a1.x; s2 += xx * a2.x; s3 += xx * a3.x;
        xx = x.y * x.y; s1 += xx * a1.y; s2 += xx * a2.y; s3 += xx * a3.y;
        xx = x.z * x.z; s1 += xx * a1.z; s2 += xx * a2.z; s3 += xx * a3.z;
        xx = x.w * x.w; s1 += xx * a1.w; s2 += xx * a2.w; s3 += xx * a3.w;
    }
#pragma unroll
    for (int o = 16; o > 0; o >>= 1) {
        s1 += __shfl_down_sync(0xFFFFFFFFu, s1, o);
        s2 += __shfl_down_sync(0xFFFFFFFFu, s2, o);
        s3 += __shfl_down_sync(0xFFFFFFFFu, s3, o);
    }
    if (lane == 0) {
        const float eps = 1e-12f;
        float n1 = fmaxf(sqrtf(s2), eps);
        float n2 = fmaxf(sqrtf(s3), eps);
        g_sim[(size_t)b * POOL + k] = s1 / (n1 * n2);
    }
}

// ---------------------------------------------------------------------------
// Kernel 3: pmt — block per (b,l): 4096 blocks x 192 threads (round-1 shape).
//   int_pmt[b,l,d] = sum_k sim[b,k] * e_p[k,l,d]
// ---------------------------------------------------------------------------
__global__ void pmt_kernel(const float* __restrict__ e_p,
                           const int*   __restrict__ task_id_p,
                           float* __restrict__ out) {
    const int task_end = (*task_id_p + 1) * NB_PT;
    const int b = blockIdx.x / PLEN;
    const int l = blockIdx.x % PLEN;
    const int d4 = threadIdx.x;          // 0..191

    const float4* ep4  = (const float4*)e_p;
    const float*  simb = g_sim + (size_t)b * POOL;

    float4 acc = make_float4(0.f, 0.f, 0.f, 0.f);
    for (int k = 0; k < task_end; k++) {
        float s  = simb[k];
        float4 v = ep4[((size_t)k * PLEN + l) * ED4 + d4];
        acc.x += s * v.x; acc.y += s * v.y;
        acc.z += s * v.z; acc.w += s * v.w;
    }

    const size_t KEY4 = (size_t)BATCH * (PLEN / 2) * ED4;
    float4* o4;
    if (l < PLEN / 2)
        o4 = (float4*)out + ((size_t)b * (PLEN / 2) + l) * ED4 + d4;
    else
        o4 = (float4*)out + KEY4 +
             ((size_t)b * (PLEN / 2) + (l - PLEN / 2)) * ED4 + d4;
    o4[0] = acc;
}

// ---------------------------------------------------------------------------
// Kernel 4: pure streaming copy (measured 89.9 us @ 6331 GB/s) — untouched.
// ---------------------------------------------------------------------------
__global__ void __launch_bounds__(256) copy_kernel(
        const float* __restrict__ x_block,
        float* __restrict__ out,
        size_t xb_float4s) {
    const float4* src = (const float4*)x_block;
    float4* dst = (float4*)(out + (size_t)BATCH * PLEN * EMBD);

    const size_t stride = (size_t)COPY_BLOCKS * 256;
    size_t i = (size_t)blockIdx.x * 256 + threadIdx.x;

    for (; i + 3 * stride < xb_float4s; i += 4 * stride) {
        float4 v0 = __ldcs(src + i);
        float4 v1 = __ldcs(src + i + stride);
        float4 v2 = __ldcs(src + i + 2 * stride);
        float4 v3 = __ldcs(src + i + 3 * stride);
        __stcs(dst + i,              v0);
        __stcs(dst + i + stride,     v1);
        __stcs(dst + i + 2 * stride, v2);
        __stcs(dst + i + 3 * stride, v3);
    }
    for (; i < xb_float4s; i += stride)
        __stcs(dst + i, __ldcs(src + i));
}

// ---------------------------------------------------------------------------
// Launch — four serial kernels, each maximally parallel for its size.
// Inputs (metadata order): x_querry, x_block, e_a, e_p, idx, task_id
// ---------------------------------------------------------------------------
extern "C" void kernel_launch(void* const* d_in, const int* in_sizes, int n_in,
                              void* d_out, int out_size) {
    const float* x_querry = (const float*)d_in[0];
    const float* x_block  = (const float*)d_in[1];
    const float* e_a      = (const float*)d_in[2];
    const float* e_p      = (const float*)d_in[3];
    const int*   task_id  = (const int*)d_in[5];
    float* out = (float*)d_out;

    wvec_kernel<<<(POOL * EMBD + 255) / 256, 256>>>(e_a, e_p);

    sim_kernel<<<(BATCH * POOL * 32) / 256, 256>>>(x_querry, task_id);

    pmt_kernel<<<BATCH * PLEN, ED4>>>(e_p, task_id, out);

    size_t xb_float4s = (size_t)in_sizes[1] / 4;
    copy_kernel<<<COPY_BLOCKS, 256>>>(x_block, out, xb_float4s);
}

// round 14
// speedup vs baseline: 1.0911x; 1.0911x over previous
#include <cuda_runtime.h>
#include <math.h>

// Problem constants (fixed by the reference)
#define POOL   100
#define NTASKS 10
#define NB_PT  (POOL / NTASKS)       // 10
#define PLEN   8
#define EMBD   768
#define BATCH  512
#define ED4    (EMBD / 4)            // 192

#define COPY_BLOCKS 2560

// Scratch (allocation-free per harness rules)
__device__ float g_sim[BATCH * POOL];
__device__ float g_w1[POOL * EMBD];  // e^2 * diag
__device__ float g_w2[POOL * EMBD];  // e^2 * diag^2
__device__ float g_w3[POOL * EMBD];  // e^2

// ---------------------------------------------------------------------------
// Kernel 1: wvec — scalar thread per (k,d): 76800 threads, 300 blocks.
//   diag = sum_l e_p[k,l,d]^2 ; w3 = e_a^2 ; w1 = w3*diag ; w2 = w1*diag.
//   8 independent coalesced loads per thread (warp = 128B lines).
// ---------------------------------------------------------------------------
__global__ void wvec_kernel(const float* __restrict__ e_a,
                            const float* __restrict__ e_p) {
    int i = blockIdx.x * blockDim.x + threadIdx.x;   // over POOL*EMBD
    if (i >= POOL * EMBD) return;
    int k = i / EMBD;
    int d = i % EMBD;

    const float* epk = e_p + (size_t)k * PLEN * EMBD + d;
    float diag = 0.f;
#pragma unroll
    for (int l = 0; l < PLEN; l++) {
        float v = epk[l * EMBD];
        diag += v * v;
    }
    float e  = e_a[i];
    float e2 = e * e;
    float w1 = e2 * diag;
    g_w3[i] = e2;
    g_w1[i] = w1;
    g_w2[i] = w1 * diag;
}

// ---------------------------------------------------------------------------
// Kernel 2: sim — warp per (b,k) pair. 6400 blocks x 256 (worst case);
// warps with pair-index >= BATCH*task_end exit. No smem, no sync.
//   sim[b,k] = Sx2w1 / (sqrt(Sx2w2)*sqrt(Sx2w3)),  x2 = xq^2.
// ---------------------------------------------------------------------------
__global__ void __launch_bounds__(256) sim_kernel(
        const float* __restrict__ x_querry,
        const int*   __restrict__ task_id_p) {
    const int task_end = (*task_id_p + 1) * NB_PT;
    const int p    = (blockIdx.x * 256 + threadIdx.x) >> 5;   // pair index
    const int lane = threadIdx.x & 31;
    if (p >= BATCH * task_end) return;
    const int b = p / task_end;
    const int k = p % task_end;
    const int row = POOL - task_end + k;

    const float4* xq4 = (const float4*)(x_querry +
                        ((size_t)b * POOL + row) * EMBD);
    const size_t kb = (size_t)k * ED4;
    const float4* w14 = (const float4*)g_w1 + kb;
    const float4* w24 = (const float4*)g_w2 + kb;
    const float4* w34 = (const float4*)g_w3 + kb;

    float s1 = 0.f, s2 = 0.f, s3 = 0.f;
#pragma unroll
    for (int j = 0; j < ED4 / 32; j++) {   // 6 iterations
        int idx = lane + j * 32;
        float4 x  = xq4[idx];
        float4 a1 = w14[idx];
        float4 a2 = w24[idx];
        float4 a3 = w34[idx];
        float xx;
        xx = x.x * x.x; s1 += xx * a1.x; s2 += xx * a2.x; s3 += xx * a3.x;
        xx = x.y * x.y; s1 += xx * a1.y; s2 += xx * a2.y; s3 += xx * a3.y;
        xx = x.z * x.z; s1 += xx * a1.z; s2 += xx * a2.z; s3 += xx * a3.z;
        xx = x.w * x.w; s1 += xx * a1.w; s2 += xx * a2.w; s3 += xx * a3.w;
    }
#pragma unroll
    for (int o = 16; o > 0; o >>= 1) {
        s1 += __shfl_down_sync(0xFFFFFFFFu, s1, o);
        s2 += __shfl_down_sync(0xFFFFFFFFu, s2, o);
        s3 += __shfl_down_sync(0xFFFFFFFFu, s3, o);
    }
    if (lane == 0) {
        const float eps = 1e-12f;
        float n1 = fmaxf(sqrtf(s2), eps);
        float n2 = fmaxf(sqrtf(s3), eps);
        g_sim[(size_t)b * POOL + k] = s1 / (n1 * n2);
    }
}

// ---------------------------------------------------------------------------
// Kernel 3: pmt — block per (b,l): 4096 blocks x 192 threads (round-1 shape).
//   int_pmt[b,l,d] = sum_k sim[b,k] * e_p[k,l,d]
// ---------------------------------------------------------------------------
__global__ void pmt_kernel(const float* __restrict__ e_p,
                           const int*   __restrict__ task_id_p,
                           float* __restrict__ out) {
    const int task_end = (*task_id_p + 1) * NB_PT;
    const int b = blockIdx.x / PLEN;
    const int l = blockIdx.x % PLEN;
    const int d4 = threadIdx.x;          // 0..191

    const float4* ep4  = (const float4*)e_p;
    const float*  simb = g_sim + (size_t)b * POOL;

    float4 acc = make_float4(0.f, 0.f, 0.f, 0.f);
    for (int k = 0; k < task_end; k++) {
        float s  = simb[k];
        float4 v = ep4[((size_t)k * PLEN + l) * ED4 + d4];
        acc.x += s * v.x; acc.y += s * v.y;
        acc.z += s * v.z; acc.w += s * v.w;
    }

    const size_t KEY4 = (size_t)BATCH * (PLEN / 2) * ED4;
    float4* o4;
    if (l < PLEN / 2)
        o4 = (float4*)out + ((size_t)b * (PLEN / 2) + l) * ED4 + d4;
    else
        o4 = (float4*)out + KEY4 +
             ((size_t)b * (PLEN / 2) + (l - PLEN / 2)) * ED4 + d4;
    o4[0] = acc;
}

// ---------------------------------------------------------------------------
// Kernel 4: pure streaming copy (measured 89.9 us @ 6331 GB/s) — untouched.
// ---------------------------------------------------------------------------
__global__ void __launch_bounds__(256) copy_kernel(
        const float* __restrict__ x_block,
        float* __restrict__ out,
        size_t xb_float4s) {
    const float4* src = (const float4*)x_block;
    float4* dst = (float4*)(out + (size_t)BATCH * PLEN * EMBD);

    const size_t stride = (size_t)COPY_BLOCKS * 256;
    size_t i = (size_t)blockIdx.x * 256 + threadIdx.x;

    for (; i + 3 * stride < xb_float4s; i += 4 * stride) {
        float4 v0 = __ldcs(src + i);
        float4 v1 = __ldcs(src + i + stride);
        float4 v2 = __ldcs(src + i + 2 * stride);
        float4 v3 = __ldcs(src + i + 3 * stride);
        __stcs(dst + i,              v0);
        __stcs(dst + i + stride,     v1);
        __stcs(dst + i + 2 * stride, v2);
        __stcs(dst + i + 3 * stride, v3);
    }
    for (; i < xb_float4s; i += stride)
        __stcs(dst + i, __ldcs(src + i));
}

// ---------------------------------------------------------------------------
// Launch — four serial kernels, each maximally parallel for its size.
// Inputs (metadata order): x_querry, x_block, e_a, e_p, idx, task_id
// ---------------------------------------------------------------------------
extern "C" void kernel_launch(void* const* d_in, const int* in_sizes, int n_in,
                              void* d_out, int out_size) {
    const float* x_querry = (const float*)d_in[0];
    const float* x_block  = (const float*)d_in[1];
    const float* e_a      = (const float*)d_in[2];
    const float* e_p      = (const float*)d_in[3];
    const int*   task_id  = (const int*)d_in[5];
    float* out = (float*)d_out;

    wvec_kernel<<<(POOL * EMBD + 255) / 256, 256>>>(e_a, e_p);

    sim_kernel<<<(BATCH * POOL * 32) / 256, 256>>>(x_querry, task_id);

    pmt_kernel<<<BATCH * PLEN, ED4>>>(e_p, task_id, out);

    size_t xb_float4s = (size_t)in_sizes[1] / 4;
    copy_kernel<<<COPY_BLOCKS, 256>>>(x_block, out, xb_float4s);
}

// round 15
// speedup vs baseline: 1.1946x; 1.0949x over previous
#include <cuda_runtime.h>
#include <math.h>

// Problem constants (fixed by the reference)
#define POOL   100
#define NTASKS 10
#define NB_PT  (POOL / NTASKS)       // 10
#define PLEN   8
#define EMBD   768
#define BATCH  512
#define ED4    (EMBD / 4)            // 192

#define SIM_G       16               // batch groups: 32 rows per block
#define SIM_THREADS 1024             // 32 warps, one row each
#define PMT_BLOCKS  BATCH            // mega: pmt first
#define COPY_BLOCKS 2560             // mega: copy after

// Scratch (allocation-free per harness rules)
__device__ float g_sim[BATCH * POOL];

// ---------------------------------------------------------------------------
// Kernel A: fused diag + sim. grid=(16, POOL), block=1024 (32 warps).
// Only task_end k-planes are active (160 blocks @ task_id=0), but each has
// 32 warps -> ~34 warps/SM. diag[k] built once per block in smem
// (e_p redundancy 160 x 27KB = 4.3 MB). One batch row per warp.
// ---------------------------------------------------------------------------
__global__ void __launch_bounds__(SIM_THREADS) sim_fused_kernel(
        const float* __restrict__ x_querry,
        const float* __restrict__ e_a,
        const float* __restrict__ e_p,
        const int*   __restrict__ task_id_p) {
    const int task_end = (*task_id_p + 1) * NB_PT;
    const int k = blockIdx.y;
    if (k >= task_end) return;

    __shared__ float s_diag[EMBD];
    __shared__ float s_ea[EMBD];

    // Phase 1: diag + ea into smem (one element per thread, tid<768)
    const float* epk = e_p + (size_t)k * PLEN * EMBD;
    for (int d = threadIdx.x; d < EMBD; d += SIM_THREADS) {
        float acc = 0.f;
#pragma unroll
        for (int l = 0; l < PLEN; l++) {
            float v = epk[l * EMBD + d];
            acc += v * v;
        }
        s_diag[d] = acc;
        s_ea[d]   = e_a[(size_t)k * EMBD + d];
    }
    __syncthreads();

    // Phase 2: one warp per batch row (32 warps -> rows b0..b0+31)
    const int warp = threadIdx.x >> 5;
    const int lane = threadIdx.x & 31;
    const int b = blockIdx.x * (BATCH / SIM_G) + warp;
    const int row = POOL - task_end + k;

    const float4* xq4 = (const float4*)(x_querry + ((size_t)b * POOL + row) * EMBD);
    const float4* ea4 = (const float4*)s_ea;
    const float4* dg4 = (const float4*)s_diag;

    float s1 = 0.f, s2 = 0.f, s3 = 0.f;
#pragma unroll
    for (int j = 0; j < ED4 / 32; j++) {   // 6 iterations
        int idx = lane + j * 32;
        float4 x = xq4[idx];
        float4 e = ea4[idx];
        float4 g = dg4[idx];
        float a, aa;
        a = x.x * e.x; aa = a * a; s3 += aa; s1 += aa * g.x; s2 += aa * g.x * g.x;
        a = x.y * e.y; aa = a * a; s3 += aa; s1 += aa * g.y; s2 += aa * g.y * g.y;
        a = x.z * e.z; aa = a * a; s3 += aa; s1 += aa * g.z; s2 += aa * g.z * g.z;
        a = x.w * e.w; aa = a * a; s3 += aa; s1 += aa * g.w; s2 += aa * g.w * g.w;
    }
#pragma unroll
    for (int o = 16; o > 0; o >>= 1) {
        s1 += __shfl_down_sync(0xFFFFFFFFu, s1, o);
        s2 += __shfl_down_sync(0xFFFFFFFFu, s2, o);
        s3 += __shfl_down_sync(0xFFFFFFFFu, s3, o);
    }
    if (lane == 0) {
        const float eps = 1e-12f;
        float n1 = fmaxf(sqrtf(s2), eps);
        float n2 = fmaxf(sqrtf(s3), eps);
        g_sim[(size_t)b * POOL + k] = s1 / (n1 * n2);
    }
}

// ---------------------------------------------------------------------------
// Kernel B: mega — proven config (95.7 us, regs 40):
//   blocks [0,512): pmt einsum; blocks [512, 3072): streaming copy.
// ---------------------------------------------------------------------------
__global__ void __launch_bounds__(256) mega_kernel(
        const float* __restrict__ e_p,
        const float* __restrict__ x_block,
        const int*   __restrict__ task_id_p,
        float* __restrict__ out,
        size_t xb_float4s) {
    if (blockIdx.x < PMT_BLOCKS) {
        // ---- einsum: int_pmt[b,l,d] = sum_k sim[b,k] * e_p[k,l,d] ----
        const int task_end = (*task_id_p + 1) * NB_PT;
        const int b = blockIdx.x;

        __shared__ float s_sim[POOL];
        if (threadIdx.x < POOL)
            s_sim[threadIdx.x] = g_sim[(size_t)b * POOL + threadIdx.x];
        __syncthreads();

        const float4* ep4 = (const float4*)e_p;
        const size_t KEY4 = (size_t)BATCH * (PLEN / 2) * ED4;

        for (int idx = threadIdx.x; idx < PLEN * ED4; idx += 256) {
            int l  = idx / ED4;
            int d4 = idx % ED4;
            float4 acc = make_float4(0.f, 0.f, 0.f, 0.f);
            for (int kk = 0; kk < task_end; kk++) {
                float s  = s_sim[kk];
                float4 v = ep4[((size_t)kk * PLEN + l) * ED4 + d4];
                acc.x += s * v.x; acc.y += s * v.y;
                acc.z += s * v.z; acc.w += s * v.w;
            }
            float4* o4;
            if (l < PLEN / 2)
                o4 = (float4*)out + ((size_t)b * (PLEN / 2) + l) * ED4 + d4;
            else
                o4 = (float4*)out + KEY4 +
                     ((size_t)b * (PLEN / 2) + (l - PLEN / 2)) * ED4 + d4;
            *o4 = acc;
        }
    } else {
        // ---- streaming copy: x_block -> out tail ----
        const float4* src = (const float4*)x_block;
        float4* dst = (float4*)(out + (size_t)BATCH * PLEN * EMBD);

        const size_t stride = (size_t)COPY_BLOCKS * 256;
        size_t i = (size_t)(blockIdx.x - PMT_BLOCKS) * 256 + threadIdx.x;

        for (; i + 3 * stride < xb_float4s; i += 4 * stride) {
            float4 v0 = __ldcs(src + i);
            float4 v1 = __ldcs(src + i + stride);
            float4 v2 = __ldcs(src + i + 2 * stride);
            float4 v3 = __ldcs(src + i + 3 * stride);
            __stcs(dst + i,              v0);
            __stcs(dst + i + stride,     v1);
            __stcs(dst + i + 2 * stride, v2);
            __stcs(dst + i + 3 * stride, v3);
        }
        for (; i < xb_float4s; i += stride)
            __stcs(dst + i, __ldcs(src + i));
    }
}

// ---------------------------------------------------------------------------
// Launch — two kernels: sim_fused -> mega(pmt+copy).
// Inputs (metadata order): x_querry, x_block, e_a, e_p, idx, task_id
// ---------------------------------------------------------------------------
extern "C" void kernel_launch(void* const* d_in, const int* in_sizes, int n_in,
                              void* d_out, int out_size) {
    const float* x_querry = (const float*)d_in[0];
    const float* x_block  = (const float*)d_in[1];
    const float* e_a      = (const float*)d_in[2];
    const float* e_p      = (const float*)d_in[3];
    const int*   task_id  = (const int*)d_in[5];
    float* out = (float*)d_out;

    dim3 sim_grid(SIM_G, POOL);
    sim_fused_kernel<<<sim_grid, SIM_THREADS>>>(x_querry, e_a, e_p, task_id);

    size_t xb_float4s = (size_t)in_sizes[1] / 4;
    mega_kernel<<<PMT_BLOCKS + COPY_BLOCKS, 256>>>(
        e_p, x_block, task_id, out, xb_float4s);
}